// round 9
// baseline (speedup 1.0000x reference)
#include <cuda_runtime.h>
#include <math.h>
#include <cstdint>

#define BATCH 256
#define NBOX 98
#define KTOP 10

// ---------------- scratch (static device globals; no allocation) ----------------
__device__ float g_A0 [12544 * 1280];      // gathered subsampled input (raw)
__device__ float g_A0h[12544 * 1280];      // A0 hi plane (fragment-major)
__device__ float g_A0l[12544 * 1280];      // A0 lo plane
__device__ float g_cwh[128 * 1280],  g_cwl[128 * 1280];     // conv_w planes
__device__ float g_f1h[4096 * 6272], g_f1l[4096 * 6272];    // fc1_w planes
__device__ float g_f2h[1536 * 4096], g_f2l[1536 * 4096];    // fc2_w planes (padded rows)
__device__ float g_a1h[256 * 6272],  g_a1l[256 * 6272];     // act1 planes
__device__ float g_h1h[256 * 4096],  g_h1l[256 * 4096];     // h1 planes
__device__ float g_part[3 * 12544 * 128];  // split-K partials (max: conv)
__device__ float g_h2[BATCH * 1470];
__device__ float g_boxes[BATCH * NBOX * 4];
__device__ float g_conf[BATCH * NBOX];
__device__ int   g_labels[BATCH * NBOX];

// ---------------- helpers -------------------------------------------------------
__device__ __forceinline__ uint32_t smem_u32(const void* p) {
    uint32_t a;
    asm("{ .reg .u64 t; cvta.to.shared.u64 t, %1; cvt.u32.u64 %0, t; }"
        : "=r"(a) : "l"(p));
    return a;
}
__device__ __forceinline__ void cp16(uint32_t dst, const void* src) {
    asm volatile("cp.async.cg.shared.global [%0], [%1], 16;" :: "r"(dst), "l"(src));
}
#define CP_COMMIT() asm volatile("cp.async.commit_group;" ::: "memory")
#define CP_WAIT1()  asm volatile("cp.async.wait_group 1;" ::: "memory")

__device__ __forceinline__ void tf32_split(float a, uint32_t& hi, uint32_t& lo) {
    uint32_t h;
    asm("cvt.rna.tf32.f32 %0, %1;" : "=r"(h) : "f"(a));
    float r = a - __uint_as_float(h);
    uint32_t l;
    asm("cvt.rna.tf32.f32 %0, %1;" : "=r"(l) : "f"(r));
    hi = h; lo = l;
}

__device__ __forceinline__ void mma_tf32(float* c, uint32_t a0, uint32_t a1,
                                         uint32_t a2, uint32_t a3,
                                         uint32_t b0, uint32_t b1) {
    asm volatile(
        "mma.sync.aligned.m16n8k8.row.col.f32.tf32.tf32.f32 "
        "{%0,%1,%2,%3}, {%4,%5,%6,%7}, {%8,%9}, {%0,%1,%2,%3};"
        : "+f"(c[0]), "+f"(c[1]), "+f"(c[2]), "+f"(c[3])
        : "r"(a0), "r"(a1), "r"(a2), "r"(a3), "r"(b0), "r"(b1));
}

// ---------------- gather: x[:, :, ::2, ::2] -> A0[m=b*49+hw][c] ------------------
__global__ void gather_kernel(const float* __restrict__ x) {
    __shared__ float tile[64][50];
    const int b  = blockIdx.y;
    const int c0 = blockIdx.x * 64;
    const int t  = threadIdx.x;
    for (int lin = t; lin < 64 * 49; lin += 256) {
        int c = lin / 49, hw = lin % 49;
        tile[c][hw] =
            x[((size_t)(b * 1280 + c0 + c) * 14 + (hw / 7) * 2) * 14 + (hw % 7) * 2];
    }
    __syncthreads();
    for (int lin = t; lin < 64 * 49; lin += 256) {
        int hw = lin >> 6, c = lin & 63;
        g_A0[((size_t)b * 49 + hw) * 1280 + c0 + c] = tile[c][hw];
    }
}

// ---------------- split: X[R][K] -> hi/lo planes in fragment-major layout --------
// plane word ((rseg*NC + c)*128 + lane*4 + v) = X[rseg*8 + lane/4][c*16 + lane%4 + 4v]
// grid: (rsegs, K/128); rows >= R are written as zero.
__global__ void split_kernel(const float* __restrict__ src, float* __restrict__ dh,
                             float* __restrict__ dl, int R, int K) {
    __shared__ float tile[1024];
    const int rseg = blockIdx.x;
    const int k0 = blockIdx.y * 128;
    const int NC = K >> 4;
    const int t = threadIdx.x;
    for (int i = t; i < 1024; i += 256) {
        int row = rseg * 8 + (i >> 7);
        tile[i] = (row < R) ? src[(size_t)row * K + k0 + (i & 127)] : 0.f;
    }
    __syncthreads();
    const size_t obase = ((size_t)rseg * NC + (k0 >> 4)) * 128;
#pragma unroll
    for (int j = 0; j < 4; j++) {
        int w = t + j * 256;
        int cc = w >> 7;
        int lane = (w >> 2) & 31;
        int v = w & 3;
        float a = tile[(lane >> 2) * 128 + cc * 16 + (lane & 3) + 4 * v];
        uint32_t hi, lo; tf32_split(a, hi, lo);
        size_t dst = obase + (size_t)cc * 128 + (w & 127);
        dh[dst] = __uint_as_float(hi);
        dl[dst] = __uint_as_float(lo);
    }
}

// ---------------- 3xTF32 GEMM on pre-split planes --------------------------------
// CTA tile 128x128, k-chunks of 16, 3-stage cp.async pipeline (32KB/stage).
// 8 warps: 2(m) x 4(n); warp tile 64x32. Consumer = pure LDS.128 + mma.
#define STAGE_WORDS 8192
#define DSMEM_BYTES (3 * STAGE_WORDS * 4)

__device__ __forceinline__ void load_stage(
    uint32_t su, int buf,
    const float* __restrict__ Ah, const float* __restrict__ Al,
    const float* __restrict__ Bh, const float* __restrict__ Bl,
    int NC, int msegB, int nsegB, int cglob, int tid)
{
    uint32_t base = su + buf * (STAGE_WORDS * 4);
    int seg = tid >> 4;
    int w0  = (tid & 15) * 8;
    size_t ga = ((size_t)(msegB + seg) * NC + cglob) * 128 + w0;
    size_t gb = ((size_t)(nsegB + seg) * NC + cglob) * 128 + w0;
    uint32_t d = base + (uint32_t)(seg * 128 + w0) * 4;
    cp16(d,                Ah + ga); cp16(d + 16,               Ah + ga + 4);
    cp16(d + 2048 * 4,     Al + ga); cp16(d + 2048 * 4 + 16,    Al + ga + 4);
    cp16(d + 4096 * 4,     Bh + gb); cp16(d + 4096 * 4 + 16,    Bh + gb + 4);
    cp16(d + 6144 * 4,     Bl + gb); cp16(d + 6144 * 4 + 16,    Bl + gb + 4);
}

__global__ void __launch_bounds__(256, 2)
gemm_mma(const float* __restrict__ Ah, const float* __restrict__ Al,
         const float* __restrict__ Bh, const float* __restrict__ Bl,
         float* __restrict__ P, int M, int K, int kc, int Npad) {
    extern __shared__ __align__(16) uint32_t sm[];
    const uint32_t su = smem_u32(sm);

    const int tid  = threadIdx.x;
    const int wid  = tid >> 5;
    const int lane = tid & 31;
    const int g    = lane >> 2;
    const int tig  = lane & 3;
    const int wm   = wid >> 2;
    const int wn   = wid & 3;

    const int NC = K >> 4;
    const int m0 = blockIdx.y * 128;
    const int n0 = blockIdx.x * 128;
    const int k0 = blockIdx.z * kc;
    const int c0 = k0 >> 4;
    const int msegB = m0 >> 3;
    const int nsegB = n0 >> 3;
    const int nstages = (min(kc, K - k0)) >> 4;

    float acc[4][4][4];
#pragma unroll
    for (int a = 0; a < 4; a++)
#pragma unroll
        for (int b = 0; b < 4; b++)
#pragma unroll
            for (int c = 0; c < 4; c++) acc[a][b][c] = 0.f;

    // prologue: stages 0,1
    load_stage(su, 0, Ah, Al, Bh, Bl, NC, msegB, nsegB, c0, tid);
    CP_COMMIT();
    if (nstages > 1)
        load_stage(su, 1, Ah, Al, Bh, Bl, NC, msegB, nsegB, c0 + 1, tid);
    CP_COMMIT();

    for (int t = 0; t < nstages; t++) {
        CP_WAIT1();
        __syncthreads();
        if (t + 2 < nstages) {
            int buf = (t + 2) % 3;
            load_stage(su, buf, Ah, Al, Bh, Bl, NC, msegB, nsegB, c0 + t + 2, tid);
        }
        CP_COMMIT();

        const uint32_t* sb = sm + (t % 3) * STAGE_WORDS;

        uint32_t Bhf[4][4], Blf[4][4];
#pragma unroll
        for (int nt = 0; nt < 4; nt++) {
            int off = (wn * 4 + nt) * 128 + lane * 4;
            *(uint4*)Bhf[nt] = *(const uint4*)&sb[4096 + off];
            *(uint4*)Blf[nt] = *(const uint4*)&sb[6144 + off];
        }

#pragma unroll
        for (int mt = 0; mt < 4; mt++) {
            int off = (wm * 8 + mt * 2) * 128 + lane * 4;
            uint4 hlo = *(const uint4*)&sb[off];
            uint4 hhi = *(const uint4*)&sb[off + 128];
            uint4 llo = *(const uint4*)&sb[2048 + off];
            uint4 lhi = *(const uint4*)&sb[2048 + off + 128];
            const uint32_t* Hlo = (const uint32_t*)&hlo;
            const uint32_t* Hhi = (const uint32_t*)&hhi;
            const uint32_t* Llo = (const uint32_t*)&llo;
            const uint32_t* Lhi = (const uint32_t*)&lhi;
#pragma unroll
            for (int s2 = 0; s2 < 2; s2++) {
                const int v0 = 2 * s2, v1 = 2 * s2 + 1;
#pragma unroll
                for (int nt = 0; nt < 4; nt++) {
                    float* c = acc[mt][nt];
                    mma_tf32(c, Hlo[v0], Hhi[v0], Hlo[v1], Hhi[v1],
                             Bhf[nt][v0], Bhf[nt][v1]);
                    mma_tf32(c, Llo[v0], Lhi[v0], Llo[v1], Lhi[v1],
                             Bhf[nt][v0], Bhf[nt][v1]);
                    mma_tf32(c, Hlo[v0], Hhi[v0], Hlo[v1], Hhi[v1],
                             Blf[nt][v0], Blf[nt][v1]);
                }
            }
        }
    }

    // ---- epilogue: write partials ----
    float* Pz = P + (size_t)blockIdx.z * M * Npad;
    const int mbase = m0 + wm * 64;
    const int nbase = n0 + wn * 32;
#pragma unroll
    for (int mt = 0; mt < 4; mt++) {
#pragma unroll
        for (int nt = 0; nt < 4; nt++) {
            float* c = acc[mt][nt];
            int r = mbase + mt * 16 + g;
            int cc = nbase + nt * 8 + tig * 2;
            *(float2*)&Pz[(size_t)r * Npad + cc]       = make_float2(c[0], c[1]);
            *(float2*)&Pz[(size_t)(r + 8) * Npad + cc] = make_float2(c[2], c[3]);
        }
    }
}

// ---------------- split-K reduces with fused epilogues + split writes -----------
__global__ void reduce_conv(const float* __restrict__ part,
                            const float* __restrict__ bias) {
    int idx = blockIdx.x * blockDim.x + threadIdx.x;
    if (idx >= 12544 * 128) return;
    const int S = 12544 * 128;
    int col = idx & 127;
    int m   = idx >> 7;
    float v = part[idx] + part[S + idx] + part[2 * S + idx] + bias[col];
    int b = m / 49, hw = m - b * 49;
    int k = col * 49 + hw;   // act1 is A[256][6272] with row b, col k
    uint32_t hi, lo; tf32_split(v, hi, lo);
    size_t w = ((size_t)(b >> 3) * 392 + (k >> 4)) * 128
             + ((b & 7) * 4 + (k & 3)) * 4 + ((k >> 2) & 3);
    g_a1h[w] = __uint_as_float(hi);
    g_a1l[w] = __uint_as_float(lo);
}

__global__ void reduce_fc1(const float* __restrict__ part,
                           const float* __restrict__ bias) {
    int idx = blockIdx.x * blockDim.x + threadIdx.x;
    if (idx >= 256 * 4096) return;
    const int S = 256 * 4096;
    int n = idx & 4095;
    int m = idx >> 12;
    float v = part[idx] + part[S + idx] + part[2 * S + idx] + part[3 * S + idx]
            + bias[n];
    v = (v >= 0.f) ? v : 0.1f * v;
    uint32_t hi, lo; tf32_split(v, hi, lo);
    size_t w = ((size_t)(m >> 3) * 256 + (n >> 4)) * 128
             + ((m & 7) * 4 + (n & 3)) * 4 + ((n >> 2) & 3);
    g_h1h[w] = __uint_as_float(hi);
    g_h1l[w] = __uint_as_float(lo);
}

__global__ void reduce_fc2(const float* __restrict__ part,
                           const float* __restrict__ bias) {
    int idx = blockIdx.x * blockDim.x + threadIdx.x;
    if (idx >= 256 * 1470) return;
    int m = idx / 1470, n = idx - m * 1470;
    float v = 0.f;
#pragma unroll
    for (int s = 0; s < 12; s++) v += part[(size_t)s * 256 * 1536 + m * 1536 + n];
    v += bias[n];
    g_h2[idx] = 1.f / (1.f + expf(-v));
}

// ---------------- decode: h2 -> boxes / conf / labels ---------------------------
__global__ void decode_kernel() {
    int idx = blockIdx.x * blockDim.x + threadIdx.x;
    if (idx >= BATCH * NBOX) return;
    int b = idx / NBOX, n = idx % NBOX;
    int cell = n >> 1;
    int gi = cell / 7, gj = cell % 7;
    const float* h = g_h2 + (size_t)b * 1470;

    float bx = h[n * 4 + 0], by = h[n * 4 + 1];
    float bw = h[n * 4 + 2], bh = h[n * 4 + 3];
    float cx = bx * 64.f + gi * 64.f;
    float cy = by * 64.f + gj * 64.f;
    float w  = bw * 448.f;
    float hh = bh * 448.f;
    float x1 = fminf(fmaxf(cx - 0.5f * w,  0.f), 448.f);
    float y1 = fminf(fmaxf(cy - 0.5f * hh, 0.f), 448.f);
    float x2 = fminf(fmaxf(cx + 0.5f * w,  0.f), 448.f);
    float y2 = fminf(fmaxf(cy + 0.5f * hh, 0.f), 448.f);

    g_boxes[idx * 4 + 0] = x1;
    g_boxes[idx * 4 + 1] = y1;
    g_boxes[idx * 4 + 2] = x2;
    g_boxes[idx * 4 + 3] = y2;
    g_conf[idx] = h[392 + n];

    const float* cl = h + 490 + cell * 20;
    float best = cl[0];
    int lab = 0;
#pragma unroll
    for (int c = 1; c < 20; c++) {
        float v = cl[c];
        if (v > best) { best = v; lab = c; }  // first max wins (matches jnp.argmax)
    }
    g_labels[idx] = lab;
}

// ---------------- NMS: one block per image --------------------------------------
__global__ void __launch_bounds__(128)
nms_kernel(float* __restrict__ out, int out_size) {
    int b = blockIdx.x;
    int t = threadIdx.x;

    __shared__ float sc[NBOX], sx1[NBOX], sy1[NBOX], sx2[NBOX], sy2[NBOX];
    __shared__ int   sl[NBOX], order[NBOX];
    __shared__ float oc[NBOX], ox1[NBOX], oy1[NBOX], ox2[NBOX], oy2[NBOX], oarea[NBOX];
    __shared__ int   ol[NBOX];
    __shared__ unsigned char keep[NBOX];

    if (t < NBOX) {
        int g = b * NBOX + t;
        sc[t]  = g_conf[g];
        sl[t]  = g_labels[g];
        sx1[t] = g_boxes[g * 4 + 0];
        sy1[t] = g_boxes[g * 4 + 1];
        sx2[t] = g_boxes[g * 4 + 2];
        sy2[t] = g_boxes[g * 4 + 3];
    }
    __syncthreads();

    if (t < NBOX) {
        float c = sc[t];
        int r = 0;
        for (int j = 0; j < NBOX; j++) {
            float cj = sc[j];
            r += (cj > c) || (cj == c && j < t);
        }
        order[r] = t;
    }
    __syncthreads();

    if (t < NBOX) {
        int s = order[t];
        oc[t] = sc[s];  ol[t] = sl[s];
        ox1[t] = sx1[s]; oy1[t] = sy1[s];
        ox2[t] = sx2[s]; oy2[t] = sy2[s];
        oarea[t] = fmaxf(ox2[t] - ox1[t], 0.f) * fmaxf(oy2[t] - oy1[t], 0.f);
        keep[t] = (oc[t] > 0.1f) ? (unsigned char)1 : (unsigned char)0;
    }
    __syncthreads();

    for (int i = 0; i < NBOX; i++) {
        if (keep[i] && t < NBOX && t > i) {
            float ix1 = fmaxf(ox1[i], ox1[t]);
            float iy1 = fmaxf(oy1[i], oy1[t]);
            float ix2 = fminf(ox2[i], ox2[t]);
            float iy2 = fminf(oy2[i], oy2[t]);
            float inter = fmaxf(ix2 - ix1, 0.f) * fmaxf(iy2 - iy1, 0.f);
            float uni = oarea[i] + oarea[t] - inter;
            float iou = (uni > 0.f) ? (inter / uni) : 0.f;
            if (iou > 0.7f) keep[t] = 0;
        }
        __syncthreads();
    }

    if (t == 0) {
        unsigned char used[NBOX];
        for (int j = 0; j < NBOX; j++) used[j] = 0;
        const int BK4 = BATCH * KTOP * 4;
        const int BK  = BATCH * KTOP;
        for (int k = 0; k < KTOP; k++) {
            float best = -2.f;
            int bi = 0;
            for (int j = 0; j < NBOX; j++) {
                if (used[j]) continue;
                float s = keep[j] ? oc[j] : -1.0f;
                if (s > best) { best = s; bi = j; }
            }
            used[bi] = 1;
            bool valid = best > 0.1f;
            int ob = (b * KTOP + k) * 4;
            if (ob + 3 < out_size) {
                out[ob + 0] = valid ? ox1[bi] : 0.f;
                out[ob + 1] = valid ? oy1[bi] : 0.f;
                out[ob + 2] = valid ? ox2[bi] : 0.f;
                out[ob + 3] = valid ? oy2[bi] : 0.f;
            }
            int ol_idx = BK4 + b * KTOP + k;
            if (ol_idx < out_size) out[ol_idx] = valid ? (float)ol[bi] : 0.f;
            int oc_idx = BK4 + BK + b * KTOP + k;
            if (oc_idx < out_size) out[oc_idx] = valid ? oc[bi] : 0.f;
        }
    }
}

// ---------------- launch ---------------------------------------------------------
extern "C" void kernel_launch(void* const* d_in, const int* in_sizes, int n_in,
                              void* d_out, int out_size) {
    const float* x      = (const float*)d_in[0];
    const float* conv_w = (const float*)d_in[1];
    const float* conv_b = (const float*)d_in[2];
    const float* fc1_w  = (const float*)d_in[3];
    const float* fc1_b  = (const float*)d_in[4];
    const float* fc2_w  = (const float*)d_in[5];
    const float* fc2_b  = (const float*)d_in[6];
    float* out = (float*)d_out;

    float *A0, *A0h, *A0l, *cwh, *cwl, *f1h, *f1l, *f2h, *f2l;
    float *a1h, *a1l, *h1h, *h1l, *part;
    cudaGetSymbolAddress((void**)&A0,  g_A0);
    cudaGetSymbolAddress((void**)&A0h, g_A0h);
    cudaGetSymbolAddress((void**)&A0l, g_A0l);
    cudaGetSymbolAddress((void**)&cwh, g_cwh);
    cudaGetSymbolAddress((void**)&cwl, g_cwl);
    cudaGetSymbolAddress((void**)&f1h, g_f1h);
    cudaGetSymbolAddress((void**)&f1l, g_f1l);
    cudaGetSymbolAddress((void**)&f2h, g_f2h);
    cudaGetSymbolAddress((void**)&f2l, g_f2l);
    cudaGetSymbolAddress((void**)&a1h, g_a1h);
    cudaGetSymbolAddress((void**)&a1l, g_a1l);
    cudaGetSymbolAddress((void**)&h1h, g_h1h);
    cudaGetSymbolAddress((void**)&h1l, g_h1l);
    cudaGetSymbolAddress((void**)&part, g_part);

    cudaFuncSetAttribute(gemm_mma, cudaFuncAttributeMaxDynamicSharedMemorySize,
                         DSMEM_BYTES);

    // 1. gather + pre-split all static operands
    gather_kernel<<<dim3(20, 256), 256>>>(x);
    split_kernel<<<dim3(1568, 10), 256>>>(A0,     A0h, A0l, 12544, 1280);
    split_kernel<<<dim3(16,   10), 256>>>(conv_w, cwh, cwl, 128,   1280);
    split_kernel<<<dim3(512,  49), 256>>>(fc1_w,  f1h, f1l, 4096,  6272);
    split_kernel<<<dim3(192,  32), 256>>>(fc2_w,  f2h, f2l, 1470,  4096);

    // 2. conv GEMM: (12544 x 1280) * (128 x 1280)^T, split-K=3 -> 294 CTAs
    gemm_mma<<<dim3(1, 98, 3), 256, DSMEM_BYTES>>>(A0h, A0l, cwh, cwl, part,
                                                   12544, 1280, 432, 128);
    reduce_conv<<<(12544 * 128 + 255) / 256, 256>>>(part, conv_b);

    // 3. fc1 GEMM: (256 x 6272) * (4096 x 6272)^T, split-K=4 -> 256 CTAs
    gemm_mma<<<dim3(32, 2, 4), 256, DSMEM_BYTES>>>(a1h, a1l, f1h, f1l, part,
                                                   256, 6272, 1568, 4096);
    reduce_fc1<<<(256 * 4096 + 255) / 256, 256>>>(part, fc1_b);

    // 4. fc2 GEMM: (256 x 4096) * (1470 x 4096)^T, split-K=12 -> 288 CTAs
    gemm_mma<<<dim3(12, 2, 12), 256, DSMEM_BYTES>>>(h1h, h1l, f2h, f2l, part,
                                                    256, 4096, 352, 1536);
    reduce_fc2<<<(256 * 1470 + 255) / 256, 256>>>(part, fc2_b);

    // 5. decode + NMS
    decode_kernel<<<(BATCH * NBOX + 255) / 256, 256>>>();
    nms_kernel<<<BATCH, 128>>>(out, out_size);
}

// round 10
// speedup vs baseline: 1.1321x; 1.1321x over previous
#include <cuda_runtime.h>
#include <math.h>
#include <cstdint>

#define BATCH 256
#define NBOX 98
#define KTOP 10

// ---------------- scratch (static device globals; no allocation) ----------------
__device__ float g_A0[12544 * 1280];       // gathered subsampled input, M x K
__device__ float g_part[3 * 12544 * 128];  // split-K partials (max consumer: conv)
__device__ float g_act1[BATCH * 6272];     // conv output in fc1-input layout
__device__ float g_h1[BATCH * 4096];       // fc1 output (post leaky relu)
__device__ float g_h2[BATCH * 1470];       // fc2 output (post sigmoid)
__device__ float g_boxes[BATCH * NBOX * 4];
__device__ float g_conf[BATCH * NBOX];
__device__ int   g_labels[BATCH * NBOX];

// ---------------- helpers -------------------------------------------------------
__device__ __forceinline__ uint32_t smem_u32(const void* p) {
    uint32_t a;
    asm("{ .reg .u64 t; cvta.to.shared.u64 t, %1; cvt.u32.u64 %0, t; }"
        : "=r"(a) : "l"(p));
    return a;
}
__device__ __forceinline__ void cp4(uint32_t dst, const void* src) {
    asm volatile("cp.async.ca.shared.global [%0], [%1], 4;" :: "r"(dst), "l"(src));
}
#define CP_COMMIT() asm volatile("cp.async.commit_group;" ::: "memory")
#define CP_WAIT2()  asm volatile("cp.async.wait_group 2;" ::: "memory")
#define CP_WAIT1()  asm volatile("cp.async.wait_group 1;" ::: "memory")

__device__ __forceinline__ void tf32_split(float a, uint32_t& hi, uint32_t& lo) {
    uint32_t h;
    asm("cvt.rna.tf32.f32 %0, %1;" : "=r"(h) : "f"(a));
    float r = a - __uint_as_float(h);
    uint32_t l;
    asm("cvt.rna.tf32.f32 %0, %1;" : "=r"(l) : "f"(r));
    hi = h; lo = l;
}

__device__ __forceinline__ void mma_tf32(float* c, uint32_t a0, uint32_t a1,
                                         uint32_t a2, uint32_t a3,
                                         uint32_t b0, uint32_t b1) {
    asm volatile(
        "mma.sync.aligned.m16n8k8.row.col.f32.tf32.tf32.f32 "
        "{%0,%1,%2,%3}, {%4,%5,%6,%7}, {%8,%9}, {%0,%1,%2,%3};"
        : "+f"(c[0]), "+f"(c[1]), "+f"(c[2]), "+f"(c[3])
        : "r"(a0), "r"(a1), "r"(a2), "r"(a3), "r"(b0), "r"(b1));
}

// ---------------- gather: x[:, :, ::2, ::2] -> A0[m=b*49+hw][c] ------------------
__global__ void gather_kernel(const float* __restrict__ x) {
    __shared__ float tile[64][50];
    const int b  = blockIdx.y;
    const int c0 = blockIdx.x * 64;
    const int t  = threadIdx.x;
    for (int lin = t; lin < 64 * 49; lin += 256) {
        int c = lin / 49, hw = lin % 49;
        tile[c][hw] =
            x[((size_t)(b * 1280 + c0 + c) * 14 + (hw / 7) * 2) * 14 + (hw % 7) * 2];
    }
    __syncthreads();
    for (int lin = t; lin < 64 * 49; lin += 256) {
        int hw = lin >> 6, c = lin & 63;
        g_A0[((size_t)b * 49 + hw) * 1280 + c0 + c] = tile[c][hw];
    }
}

// ---------------- 3xTF32 mma.sync GEMM, in-smem split staging --------------------
// CTA tile 128x128, k-chunks of 16.
// 3 raw buffers (4096 words = A 2048 + B 2048, fragment-major, cp.async targets)
// 2 plane buffers (8192 words: Ah@0, Al@2048, Bh@4096, Bl@6144)
// Per stage: loader cp.async raw -> split phase (1x per element) -> pure LDS+mma.
#define RAW_WORDS   4096
#define PLANE_WORDS 8192
#define PLANE_BASE  (3 * RAW_WORDS)                      // word offset 12288
#define DSMEM_BYTES ((3 * RAW_WORDS + 2 * PLANE_WORDS) * 4)  // 114688 B

__device__ __forceinline__ void load_raw(
    uint32_t su, int buf, const float* __restrict__ A, const float* __restrict__ B,
    int K, const int* rowA, const int* rowB, int kb, int wid, int lane, int tig)
{
    uint32_t base = su + buf * (RAW_WORDS * 4);
#pragma unroll
    for (int i = 0; i < 2; i++) {
        int seg = wid + i * 8;
        uint32_t da = base + (uint32_t)(seg * 128 + lane * 4) * 4;
        uint32_t db = da + 2048 * 4;
        const float* sa = A + (size_t)rowA[i] * K + kb + tig;
        const float* sb = B + (size_t)rowB[i] * K + kb + tig;
#pragma unroll
        for (int v = 0; v < 4; v++) {
            cp4(da + v * 4, sa + 4 * v);
            cp4(db + v * 4, sb + 4 * v);
        }
    }
}

__device__ __forceinline__ void split_stage(const uint32_t* __restrict__ raw,
                                            uint32_t* __restrict__ plane, int tid)
{
    const int w0 = tid * 16;                       // 16 contiguous raw words
    const uint32_t* src = raw + w0;
    uint32_t* dh = plane + ((w0 < 2048) ? w0 : (2048 + w0));  // A->+0, B->+4096
    uint32_t* dl = dh + 2048;                                  // Al / Bl
#pragma unroll
    for (int j = 0; j < 4; j++) {
        uint4 r = ((const uint4*)src)[j];
        uint4 h, l;
        tf32_split(__uint_as_float(r.x), h.x, l.x);
        tf32_split(__uint_as_float(r.y), h.y, l.y);
        tf32_split(__uint_as_float(r.z), h.z, l.z);
        tf32_split(__uint_as_float(r.w), h.w, l.w);
        ((uint4*)dh)[j] = h;
        ((uint4*)dl)[j] = l;
    }
}

__global__ void __launch_bounds__(256, 2)
gemm_mma(const float* __restrict__ A, const float* __restrict__ B,
         float* __restrict__ P, int M, int N, int K, int kc, int Npad) {
    extern __shared__ __align__(16) uint32_t sm[];
    const uint32_t su = smem_u32(sm);

    const int tid  = threadIdx.x;
    const int wid  = tid >> 5;
    const int lane = tid & 31;
    const int g    = lane >> 2;
    const int tig  = lane & 3;
    const int wm   = wid >> 2;
    const int wn   = wid & 3;

    const int m0 = blockIdx.y * 128;
    const int n0 = blockIdx.x * 128;
    const int k0 = blockIdx.z * kc;
    const int nstages = (min(kc, K - k0)) >> 4;

    int rowA[2], rowB[2];
#pragma unroll
    for (int i = 0; i < 2; i++) {
        int sA = wid + i * 8;
        rowA[i] = m0 + (sA >> 1) * 16 + (sA & 1) * 8 + g;
        int nr = n0 + (wid + i * 8) * 8 + g;
        rowB[i] = (nr < N) ? nr : (N - 1);
    }

    float acc[4][4][4];
#pragma unroll
    for (int a = 0; a < 4; a++)
#pragma unroll
        for (int b = 0; b < 4; b++)
#pragma unroll
            for (int c = 0; c < 4; c++) acc[a][b][c] = 0.f;

    // ---- prologue: land raw 0..2, split 0 and 1 ----
#pragma unroll
    for (int s = 0; s < 3; s++) {
        if (s < nstages) load_raw(su, s, A, B, K, rowA, rowB, k0 + s * 16,
                                  wid, lane, tig);
        CP_COMMIT();
    }
    CP_WAIT2();
    __syncthreads();
    split_stage(sm, sm + PLANE_BASE, tid);
    CP_WAIT1();
    __syncthreads();
    if (nstages > 1)
        split_stage(sm + RAW_WORDS, sm + PLANE_BASE + PLANE_WORDS, tid);
    __syncthreads();

    for (int t = 0; t < nstages; t++) {
        const uint32_t* sb = sm + PLANE_BASE + (t & 1) * PLANE_WORDS;

        // ---- compute stage t: pure LDS.128 + mma ----
        uint32_t Bhf[4][4], Blf[4][4];
#pragma unroll
        for (int nt = 0; nt < 4; nt++) {
            int off = (wn * 4 + nt) * 128 + lane * 4;
            *(uint4*)Bhf[nt] = *(const uint4*)&sb[4096 + off];
            *(uint4*)Blf[nt] = *(const uint4*)&sb[6144 + off];
        }
#pragma unroll
        for (int mt = 0; mt < 4; mt++) {
            int off = (wm * 8 + mt * 2) * 128 + lane * 4;
            uint4 hlo = *(const uint4*)&sb[off];
            uint4 hhi = *(const uint4*)&sb[off + 128];
            uint4 llo = *(const uint4*)&sb[2048 + off];
            uint4 lhi = *(const uint4*)&sb[2048 + off + 128];
            const uint32_t* Hlo = (const uint32_t*)&hlo;
            const uint32_t* Hhi = (const uint32_t*)&hhi;
            const uint32_t* Llo = (const uint32_t*)&llo;
            const uint32_t* Lhi = (const uint32_t*)&lhi;
#pragma unroll
            for (int s2 = 0; s2 < 2; s2++) {
                const int v0 = 2 * s2, v1 = 2 * s2 + 1;
#pragma unroll
                for (int nt = 0; nt < 4; nt++) {
                    float* c = acc[mt][nt];
                    mma_tf32(c, Hlo[v0], Hhi[v0], Hlo[v1], Hhi[v1],
                             Bhf[nt][v0], Bhf[nt][v1]);
                    mma_tf32(c, Llo[v0], Lhi[v0], Llo[v1], Lhi[v1],
                             Bhf[nt][v0], Bhf[nt][v1]);
                    mma_tf32(c, Hlo[v0], Hhi[v0], Hlo[v1], Hhi[v1],
                             Blf[nt][v0], Blf[nt][v1]);
                }
            }
        }
        __syncthreads();   // all warps done reading plane[t&1]

        // ---- prefetch raw t+3, split raw t+2 into plane[t&1] ----
        if (t + 3 < nstages)
            load_raw(su, (t + 3) % 3, A, B, K, rowA, rowB, k0 + (t + 3) * 16,
                     wid, lane, tig);
        CP_COMMIT();
        if (t + 2 < nstages) {
            CP_WAIT1();
            __syncthreads();   // raw t+2 visible to all threads
            split_stage(sm + ((t + 2) % 3) * RAW_WORDS,
                        sm + PLANE_BASE + (t & 1) * PLANE_WORDS, tid);
        }
        // plane[t&1] (stage t+2) becomes visible via the sync at top of iter t+1
    }

    // ---- epilogue: write partials ----
    float* Pz = P + (size_t)blockIdx.z * M * Npad;
    const int mbase = m0 + wm * 64;
    const int nbase = n0 + wn * 32;
#pragma unroll
    for (int mt = 0; mt < 4; mt++) {
#pragma unroll
        for (int nt = 0; nt < 4; nt++) {
            float* c = acc[mt][nt];
            int r = mbase + mt * 16 + g;
            int cc = nbase + nt * 8 + tig * 2;
            *(float2*)&Pz[(size_t)r * Npad + cc]       = make_float2(c[0], c[1]);
            *(float2*)&Pz[(size_t)(r + 8) * Npad + cc] = make_float2(c[2], c[3]);
        }
    }
}

// ---------------- split-K reduces with fused epilogues --------------------------
__global__ void reduce_conv(const float* __restrict__ part,
                            const float* __restrict__ bias) {
    int idx = blockIdx.x * blockDim.x + threadIdx.x;
    if (idx >= 12544 * 128) return;
    const int S = 12544 * 128;
    int col = idx & 127;
    int m   = idx >> 7;
    float v = part[idx] + part[S + idx] + part[2 * S + idx] + bias[col];
    int b = m / 49, hw = m - b * 49;
    g_act1[(size_t)b * 6272 + col * 49 + hw] = v;
}

__global__ void reduce_fc1(const float* __restrict__ part,
                           const float* __restrict__ bias) {
    int idx = blockIdx.x * blockDim.x + threadIdx.x;
    if (idx >= 256 * 4096) return;
    const int S = 256 * 4096;
    int n = idx & 4095;
    float v = part[idx] + part[S + idx] + part[2 * S + idx] + part[3 * S + idx]
            + bias[n];
    g_h1[idx] = (v >= 0.f) ? v : 0.1f * v;
}

__global__ void reduce_fc2(const float* __restrict__ part,
                           const float* __restrict__ bias) {
    int idx = blockIdx.x * blockDim.x + threadIdx.x;
    if (idx >= 256 * 1470) return;
    int m = idx / 1470, n = idx - m * 1470;
    float v = 0.f;
#pragma unroll
    for (int s = 0; s < 12; s++) v += part[(size_t)s * 256 * 1536 + m * 1536 + n];
    v += bias[n];
    g_h2[idx] = 1.f / (1.f + expf(-v));
}

// ---------------- decode: h2 -> boxes / conf / labels ---------------------------
__global__ void decode_kernel() {
    int idx = blockIdx.x * blockDim.x + threadIdx.x;
    if (idx >= BATCH * NBOX) return;
    int b = idx / NBOX, n = idx % NBOX;
    int cell = n >> 1;
    int gi = cell / 7, gj = cell % 7;
    const float* h = g_h2 + (size_t)b * 1470;

    float bx = h[n * 4 + 0], by = h[n * 4 + 1];
    float bw = h[n * 4 + 2], bh = h[n * 4 + 3];
    float cx = bx * 64.f + gi * 64.f;
    float cy = by * 64.f + gj * 64.f;
    float w  = bw * 448.f;
    float hh = bh * 448.f;
    float x1 = fminf(fmaxf(cx - 0.5f * w,  0.f), 448.f);
    float y1 = fminf(fmaxf(cy - 0.5f * hh, 0.f), 448.f);
    float x2 = fminf(fmaxf(cx + 0.5f * w,  0.f), 448.f);
    float y2 = fminf(fmaxf(cy + 0.5f * hh, 0.f), 448.f);

    g_boxes[idx * 4 + 0] = x1;
    g_boxes[idx * 4 + 1] = y1;
    g_boxes[idx * 4 + 2] = x2;
    g_boxes[idx * 4 + 3] = y2;
    g_conf[idx] = h[392 + n];

    const float* cl = h + 490 + cell * 20;
    float best = cl[0];
    int lab = 0;
#pragma unroll
    for (int c = 1; c < 20; c++) {
        float v = cl[c];
        if (v > best) { best = v; lab = c; }  // first max wins (matches jnp.argmax)
    }
    g_labels[idx] = lab;
}

// ---------------- NMS: one block per image --------------------------------------
__global__ void __launch_bounds__(128)
nms_kernel(float* __restrict__ out, int out_size) {
    int b = blockIdx.x;
    int t = threadIdx.x;

    __shared__ float sc[NBOX], sx1[NBOX], sy1[NBOX], sx2[NBOX], sy2[NBOX];
    __shared__ int   sl[NBOX], order[NBOX];
    __shared__ float oc[NBOX], ox1[NBOX], oy1[NBOX], ox2[NBOX], oy2[NBOX], oarea[NBOX];
    __shared__ int   ol[NBOX];
    __shared__ unsigned char keep[NBOX];

    if (t < NBOX) {
        int g = b * NBOX + t;
        sc[t]  = g_conf[g];
        sl[t]  = g_labels[g];
        sx1[t] = g_boxes[g * 4 + 0];
        sy1[t] = g_boxes[g * 4 + 1];
        sx2[t] = g_boxes[g * 4 + 2];
        sy2[t] = g_boxes[g * 4 + 3];
    }
    __syncthreads();

    if (t < NBOX) {
        float c = sc[t];
        int r = 0;
        for (int j = 0; j < NBOX; j++) {
            float cj = sc[j];
            r += (cj > c) || (cj == c && j < t);
        }
        order[r] = t;
    }
    __syncthreads();

    if (t < NBOX) {
        int s = order[t];
        oc[t] = sc[s];  ol[t] = sl[s];
        ox1[t] = sx1[s]; oy1[t] = sy1[s];
        ox2[t] = sx2[s]; oy2[t] = sy2[s];
        oarea[t] = fmaxf(ox2[t] - ox1[t], 0.f) * fmaxf(oy2[t] - oy1[t], 0.f);
        keep[t] = (oc[t] > 0.1f) ? (unsigned char)1 : (unsigned char)0;
    }
    __syncthreads();

    for (int i = 0; i < NBOX; i++) {
        if (keep[i] && t < NBOX && t > i) {
            float ix1 = fmaxf(ox1[i], ox1[t]);
            float iy1 = fmaxf(oy1[i], oy1[t]);
            float ix2 = fminf(ox2[i], ox2[t]);
            float iy2 = fminf(oy2[i], oy2[t]);
            float inter = fmaxf(ix2 - ix1, 0.f) * fmaxf(iy2 - iy1, 0.f);
            float uni = oarea[i] + oarea[t] - inter;
            float iou = (uni > 0.f) ? (inter / uni) : 0.f;
            if (iou > 0.7f) keep[t] = 0;
        }
        __syncthreads();
    }

    if (t == 0) {
        unsigned char used[NBOX];
        for (int j = 0; j < NBOX; j++) used[j] = 0;
        const int BK4 = BATCH * KTOP * 4;
        const int BK  = BATCH * KTOP;
        for (int k = 0; k < KTOP; k++) {
            float best = -2.f;
            int bi = 0;
            for (int j = 0; j < NBOX; j++) {
                if (used[j]) continue;
                float s = keep[j] ? oc[j] : -1.0f;
                if (s > best) { best = s; bi = j; }
            }
            used[bi] = 1;
            bool valid = best > 0.1f;
            int ob = (b * KTOP + k) * 4;
            if (ob + 3 < out_size) {
                out[ob + 0] = valid ? ox1[bi] : 0.f;
                out[ob + 1] = valid ? oy1[bi] : 0.f;
                out[ob + 2] = valid ? ox2[bi] : 0.f;
                out[ob + 3] = valid ? oy2[bi] : 0.f;
            }
            int ol_idx = BK4 + b * KTOP + k;
            if (ol_idx < out_size) out[ol_idx] = valid ? (float)ol[bi] : 0.f;
            int oc_idx = BK4 + BK + b * KTOP + k;
            if (oc_idx < out_size) out[oc_idx] = valid ? oc[bi] : 0.f;
        }
    }
}

// ---------------- launch ---------------------------------------------------------
extern "C" void kernel_launch(void* const* d_in, const int* in_sizes, int n_in,
                              void* d_out, int out_size) {
    const float* x      = (const float*)d_in[0];
    const float* conv_w = (const float*)d_in[1];
    const float* conv_b = (const float*)d_in[2];
    const float* fc1_w  = (const float*)d_in[3];
    const float* fc1_b  = (const float*)d_in[4];
    const float* fc2_w  = (const float*)d_in[5];
    const float* fc2_b  = (const float*)d_in[6];
    float* out = (float*)d_out;

    float *A0, *part, *act1, *h1;
    cudaGetSymbolAddress((void**)&A0,   g_A0);
    cudaGetSymbolAddress((void**)&part, g_part);
    cudaGetSymbolAddress((void**)&act1, g_act1);
    cudaGetSymbolAddress((void**)&h1,   g_h1);

    cudaFuncSetAttribute(gemm_mma, cudaFuncAttributeMaxDynamicSharedMemorySize,
                         DSMEM_BYTES);

    // 1. gather subsampled input (smem transpose, coalesced writes)
    gather_kernel<<<dim3(20, 256), 256>>>(x);

    // 2. conv GEMM: (12544 x 1280) * (128 x 1280)^T, split-K=3 -> 294 CTAs
    gemm_mma<<<dim3(1, 98, 3), 256, DSMEM_BYTES>>>(A0, conv_w, part,
                                                   12544, 128, 1280, 432, 128);
    reduce_conv<<<(12544 * 128 + 255) / 256, 256>>>(part, conv_b);

    // 3. fc1 GEMM: (256 x 6272) * (4096 x 6272)^T, split-K=4 -> 256 CTAs
    gemm_mma<<<dim3(32, 2, 4), 256, DSMEM_BYTES>>>(act1, fc1_w, part,
                                                   256, 4096, 6272, 1568, 4096);
    reduce_fc1<<<(256 * 4096 + 255) / 256, 256>>>(part, fc1_b);

    // 4. fc2 GEMM: (256 x 4096) * (1470 x 4096)^T, split-K=12 -> 288 CTAs
    gemm_mma<<<dim3(12, 2, 12), 256, DSMEM_BYTES>>>(h1, fc2_w, part,
                                                    256, 1470, 4096, 352, 1536);
    reduce_fc2<<<(256 * 1470 + 255) / 256, 256>>>(part, fc2_b);

    // 5. decode + NMS
    decode_kernel<<<(BATCH * NBOX + 255) / 256, 256>>>();
    nms_kernel<<<BATCH, 128>>>(out, out_size);
}

// round 11
// speedup vs baseline: 1.8367x; 1.6223x over previous
#include <cuda_runtime.h>
#include <math.h>
#include <cstdint>

#define BATCH 256
#define NBOX 98
#define KTOP 10

// ---------------- scratch (static device globals; no allocation) ----------------
__device__ float g_A0[12544 * 1280];       // gathered subsampled input, M x K
__device__ float g_part[3 * 12544 * 128];  // split-K partials (max consumer: conv)
__device__ float g_act1[BATCH * 6272];     // conv output in fc1-input layout
__device__ float g_h1[BATCH * 4096];       // fc1 output (post leaky relu)
__device__ float g_h2[BATCH * 1470];       // fc2 output (post sigmoid)
__device__ float g_boxes[BATCH * NBOX * 4];
__device__ float g_conf[BATCH * NBOX];
__device__ int   g_labels[BATCH * NBOX];

// ---------------- helpers -------------------------------------------------------
__device__ __forceinline__ uint32_t smem_u32(const void* p) {
    uint32_t a;
    asm("{ .reg .u64 t; cvta.to.shared.u64 t, %1; cvt.u32.u64 %0, t; }"
        : "=r"(a) : "l"(p));
    return a;
}
__device__ __forceinline__ void cp4(uint32_t dst, const void* src) {
    asm volatile("cp.async.ca.shared.global [%0], [%1], 4;" :: "r"(dst), "l"(src));
}
#define CP_COMMIT() asm volatile("cp.async.commit_group;" ::: "memory")
#define CP_WAIT2()  asm volatile("cp.async.wait_group 2;" ::: "memory")

// Fast 3xTF32 split: the tensor core reads only the 19 tf32 bits of a .b32
// operand (low 13 mantissa bits ignored). hi = a with low 13 bits masked
// (== what the MMA will consume); r = a - hi is exact (Sterbenz); r is fed
// raw as lo — the MMA truncates it itself. 2 lat-4 ops vs 2x cvt(20)+fsub.
__device__ __forceinline__ void tf32_split(float a, uint32_t& hi, uint32_t& lo) {
    uint32_t ab = __float_as_uint(a) & 0xFFFFE000u;
    hi = ab;
    lo = __float_as_uint(a - __uint_as_float(ab));
}

__device__ __forceinline__ void mma_tf32(float* c, uint32_t a0, uint32_t a1,
                                         uint32_t a2, uint32_t a3,
                                         uint32_t b0, uint32_t b1) {
    asm volatile(
        "mma.sync.aligned.m16n8k8.row.col.f32.tf32.tf32.f32 "
        "{%0,%1,%2,%3}, {%4,%5,%6,%7}, {%8,%9}, {%0,%1,%2,%3};"
        : "+f"(c[0]), "+f"(c[1]), "+f"(c[2]), "+f"(c[3])
        : "r"(a0), "r"(a1), "r"(a2), "r"(a3), "r"(b0), "r"(b1));
}

// ---------------- gather: x[:, :, ::2, ::2] -> A0[m=b*49+hw][c] ------------------
__global__ void gather_kernel(const float* __restrict__ x) {
    __shared__ float tile[64][50];
    const int b  = blockIdx.y;
    const int c0 = blockIdx.x * 64;
    const int t  = threadIdx.x;
    for (int lin = t; lin < 64 * 49; lin += 256) {
        int c = lin / 49, hw = lin % 49;
        tile[c][hw] =
            x[((size_t)(b * 1280 + c0 + c) * 14 + (hw / 7) * 2) * 14 + (hw % 7) * 2];
    }
    __syncthreads();
    for (int lin = t; lin < 64 * 49; lin += 256) {
        int hw = lin >> 6, c = lin & 63;
        g_A0[((size_t)b * 49 + hw) * 1280 + c0 + c] = tile[c][hw];
    }
}

// ---------------- 3xTF32 mma.sync GEMM with cp.async pipeline --------------------
// CTA tile 128x128, K staged in chunks of 16, 4-stage cp.async pipeline.
// 8 warps: 2(m) x 4(n); warp tile 64x32.
// smem per stage (raw fp32, fragment-major): A 16 segs x 512B, B 16 segs x 512B.
// Stage s at word s*4096: A @ +0, B @ +2048. seg = 128 words = 32 lanes x 16B.
// __launch_bounds__(256, 2): 128 regs + 64KB smem -> 2 CTAs/SM; grids > 148.
#define STAGE_WORDS 4096
#define DSMEM_BYTES (4 * STAGE_WORDS * 4)

__device__ __forceinline__ void load_stage(
    uint32_t su, int buf, const float* __restrict__ A, const float* __restrict__ B,
    int K, const int* rowA, const int* rowB, int kb, int wid, int lane, int tig)
{
    uint32_t base = su + buf * (STAGE_WORDS * 4);
#pragma unroll
    for (int i = 0; i < 2; i++) {
        int seg = wid + i * 8;
        uint32_t da = base + (uint32_t)(seg * 128 + lane * 4) * 4;
        uint32_t db = da + 2048 * 4;
        const float* sa = A + (size_t)rowA[i] * K + kb + tig;
        const float* sb = B + (size_t)rowB[i] * K + kb + tig;
#pragma unroll
        for (int v = 0; v < 4; v++) {
            cp4(da + v * 4, sa + 4 * v);
            cp4(db + v * 4, sb + 4 * v);
        }
    }
}

__global__ void __launch_bounds__(256, 2)
gemm_mma(const float* __restrict__ A, const float* __restrict__ B,
         float* __restrict__ P, int M, int N, int K, int kc, int Npad) {
    extern __shared__ __align__(16) uint32_t sm[];
    const uint32_t su = smem_u32(sm);

    const int tid  = threadIdx.x;
    const int wid  = tid >> 5;
    const int lane = tid & 31;
    const int g    = lane >> 2;
    const int tig  = lane & 3;
    const int wm   = wid >> 2;
    const int wn   = wid & 3;

    const int m0 = blockIdx.y * 128;
    const int n0 = blockIdx.x * 128;
    const int k0 = blockIdx.z * kc;
    const int nstages = (min(kc, K - k0)) >> 4;

    int rowA[2], rowB[2];
#pragma unroll
    for (int i = 0; i < 2; i++) {
        int sA = wid + i * 8;
        rowA[i] = m0 + (sA >> 1) * 16 + (sA & 1) * 8 + g;
        int nr = n0 + (wid + i * 8) * 8 + g;
        rowB[i] = (nr < N) ? nr : (N - 1);
    }

    float acc[4][4][4];
#pragma unroll
    for (int a = 0; a < 4; a++)
#pragma unroll
        for (int b = 0; b < 4; b++)
#pragma unroll
            for (int c = 0; c < 4; c++) acc[a][b][c] = 0.f;

    // prologue: issue stages 0..2
#pragma unroll
    for (int s = 0; s < 3; s++) {
        if (s < nstages) load_stage(su, s, A, B, K, rowA, rowB, k0 + s * 16,
                                    wid, lane, tig);
        CP_COMMIT();
    }

    for (int t = 0; t < nstages; t++) {
        CP_WAIT2();
        __syncthreads();
        if (t + 3 < nstages)
            load_stage(su, (t + 3) & 3, A, B, K, rowA, rowB, k0 + (t + 3) * 16,
                       wid, lane, tig);
        CP_COMMIT();

        const uint32_t* sb = sm + (t & 3) * STAGE_WORDS;

        // ---- B fragments: load raw, mask/sub split ----
        uint32_t Bh[4][4], Bl[4][4];
#pragma unroll
        for (int nt = 0; nt < 4; nt++) {
            uint4 raw = *(const uint4*)&sb[2048 + (wn * 4 + nt) * 128 + lane * 4];
            const float* f = (const float*)&raw;
#pragma unroll
            for (int v = 0; v < 4; v++) tf32_split(f[v], Bh[nt][v], Bl[nt][v]);
        }

#pragma unroll
        for (int mt = 0; mt < 4; mt++) {
            int segLo = ((wm * 4 + mt) * 2) * 128;
            uint4 rlo = *(const uint4*)&sb[segLo + lane * 4];
            uint4 rhi = *(const uint4*)&sb[segLo + 128 + lane * 4];
            const float* flo = (const float*)&rlo;
            const float* fhi = (const float*)&rhi;
            uint32_t HLh[4], HLl[4], HHh[4], HHl[4];
#pragma unroll
            for (int v = 0; v < 4; v++) {
                tf32_split(flo[v], HLh[v], HLl[v]);
                tf32_split(fhi[v], HHh[v], HHl[v]);
            }
#pragma unroll
            for (int s2 = 0; s2 < 2; s2++) {
                const int v0 = 2 * s2, v1 = 2 * s2 + 1;
#pragma unroll
                for (int nt = 0; nt < 4; nt++) {
                    float* c = acc[mt][nt];
                    mma_tf32(c, HLh[v0], HHh[v0], HLh[v1], HHh[v1],
                             Bh[nt][v0], Bh[nt][v1]);
                    mma_tf32(c, HLl[v0], HHl[v0], HLl[v1], HHl[v1],
                             Bh[nt][v0], Bh[nt][v1]);
                    mma_tf32(c, HLh[v0], HHh[v0], HLh[v1], HHh[v1],
                             Bl[nt][v0], Bl[nt][v1]);
                }
            }
        }
    }

    // ---- epilogue: write partials ----
    float* Pz = P + (size_t)blockIdx.z * M * Npad;
    const int mbase = m0 + wm * 64;
    const int nbase = n0 + wn * 32;
#pragma unroll
    for (int mt = 0; mt < 4; mt++) {
#pragma unroll
        for (int nt = 0; nt < 4; nt++) {
            float* c = acc[mt][nt];
            int r = mbase + mt * 16 + g;
            int cc = nbase + nt * 8 + tig * 2;
            *(float2*)&Pz[(size_t)r * Npad + cc]       = make_float2(c[0], c[1]);
            *(float2*)&Pz[(size_t)(r + 8) * Npad + cc] = make_float2(c[2], c[3]);
        }
    }
}

// ---------------- split-K reduces with fused epilogues --------------------------
__global__ void reduce_conv(const float* __restrict__ part,
                            const float* __restrict__ bias) {
    int idx = blockIdx.x * blockDim.x + threadIdx.x;
    if (idx >= 12544 * 128) return;
    const int S = 12544 * 128;
    int col = idx & 127;
    int m   = idx >> 7;
    float v = part[idx] + part[S + idx] + part[2 * S + idx] + bias[col];
    int b = m / 49, hw = m - b * 49;
    g_act1[(size_t)b * 6272 + col * 49 + hw] = v;
}

__global__ void reduce_fc1(const float* __restrict__ part,
                           const float* __restrict__ bias) {
    int idx = blockIdx.x * blockDim.x + threadIdx.x;
    if (idx >= 256 * 4096) return;
    const int S = 256 * 4096;
    int n = idx & 4095;
    float v = part[idx] + part[S + idx] + part[2 * S + idx] + part[3 * S + idx]
            + bias[n];
    g_h1[idx] = (v >= 0.f) ? v : 0.1f * v;
}

__global__ void reduce_fc2(const float* __restrict__ part,
                           const float* __restrict__ bias) {
    int idx = blockIdx.x * blockDim.x + threadIdx.x;
    if (idx >= 256 * 1470) return;
    int m = idx / 1470, n = idx - m * 1470;
    float v = 0.f;
#pragma unroll
    for (int s = 0; s < 12; s++) v += part[(size_t)s * 256 * 1536 + m * 1536 + n];
    v += bias[n];
    g_h2[idx] = 1.f / (1.f + expf(-v));
}

// ---------------- decode: h2 -> boxes / conf / labels ---------------------------
__global__ void decode_kernel() {
    int idx = blockIdx.x * blockDim.x + threadIdx.x;
    if (idx >= BATCH * NBOX) return;
    int b = idx / NBOX, n = idx % NBOX;
    int cell = n >> 1;
    int gi = cell / 7, gj = cell % 7;
    const float* h = g_h2 + (size_t)b * 1470;

    float bx = h[n * 4 + 0], by = h[n * 4 + 1];
    float bw = h[n * 4 + 2], bh = h[n * 4 + 3];
    float cx = bx * 64.f + gi * 64.f;
    float cy = by * 64.f + gj * 64.f;
    float w  = bw * 448.f;
    float hh = bh * 448.f;
    float x1 = fminf(fmaxf(cx - 0.5f * w,  0.f), 448.f);
    float y1 = fminf(fmaxf(cy - 0.5f * hh, 0.f), 448.f);
    float x2 = fminf(fmaxf(cx + 0.5f * w,  0.f), 448.f);
    float y2 = fminf(fmaxf(cy + 0.5f * hh, 0.f), 448.f);

    g_boxes[idx * 4 + 0] = x1;
    g_boxes[idx * 4 + 1] = y1;
    g_boxes[idx * 4 + 2] = x2;
    g_boxes[idx * 4 + 3] = y2;
    g_conf[idx] = h[392 + n];

    const float* cl = h + 490 + cell * 20;
    float best = cl[0];
    int lab = 0;
#pragma unroll
    for (int c = 1; c < 20; c++) {
        float v = cl[c];
        if (v > best) { best = v; lab = c; }  // first max wins (matches jnp.argmax)
    }
    g_labels[idx] = lab;
}

// ---------------- NMS: one block per image --------------------------------------
__global__ void __launch_bounds__(128)
nms_kernel(float* __restrict__ out, int out_size) {
    int b = blockIdx.x;
    int t = threadIdx.x;

    __shared__ float sc[NBOX], sx1[NBOX], sy1[NBOX], sx2[NBOX], sy2[NBOX];
    __shared__ int   sl[NBOX], order[NBOX];
    __shared__ float oc[NBOX], ox1[NBOX], oy1[NBOX], ox2[NBOX], oy2[NBOX], oarea[NBOX];
    __shared__ int   ol[NBOX];
    __shared__ unsigned char keep[NBOX];

    if (t < NBOX) {
        int g = b * NBOX + t;
        sc[t]  = g_conf[g];
        sl[t]  = g_labels[g];
        sx1[t] = g_boxes[g * 4 + 0];
        sy1[t] = g_boxes[g * 4 + 1];
        sx2[t] = g_boxes[g * 4 + 2];
        sy2[t] = g_boxes[g * 4 + 3];
    }
    __syncthreads();

    if (t < NBOX) {
        float c = sc[t];
        int r = 0;
        for (int j = 0; j < NBOX; j++) {
            float cj = sc[j];
            r += (cj > c) || (cj == c && j < t);
        }
        order[r] = t;
    }
    __syncthreads();

    if (t < NBOX) {
        int s = order[t];
        oc[t] = sc[s];  ol[t] = sl[s];
        ox1[t] = sx1[s]; oy1[t] = sy1[s];
        ox2[t] = sx2[s]; oy2[t] = sy2[s];
        oarea[t] = fmaxf(ox2[t] - ox1[t], 0.f) * fmaxf(oy2[t] - oy1[t], 0.f);
        keep[t] = (oc[t] > 0.1f) ? (unsigned char)1 : (unsigned char)0;
    }
    __syncthreads();

    for (int i = 0; i < NBOX; i++) {
        if (keep[i] && t < NBOX && t > i) {
            float ix1 = fmaxf(ox1[i], ox1[t]);
            float iy1 = fmaxf(oy1[i], oy1[t]);
            float ix2 = fminf(ox2[i], ox2[t]);
            float iy2 = fminf(oy2[i], oy2[t]);
            float inter = fmaxf(ix2 - ix1, 0.f) * fmaxf(iy2 - iy1, 0.f);
            float uni = oarea[i] + oarea[t] - inter;
            float iou = (uni > 0.f) ? (inter / uni) : 0.f;
            if (iou > 0.7f) keep[t] = 0;
        }
        __syncthreads();
    }

    if (t == 0) {
        unsigned char used[NBOX];
        for (int j = 0; j < NBOX; j++) used[j] = 0;
        const int BK4 = BATCH * KTOP * 4;
        const int BK  = BATCH * KTOP;
        for (int k = 0; k < KTOP; k++) {
            float best = -2.f;
            int bi = 0;
            for (int j = 0; j < NBOX; j++) {
                if (used[j]) continue;
                float s = keep[j] ? oc[j] : -1.0f;
                if (s > best) { best = s; bi = j; }
            }
            used[bi] = 1;
            bool valid = best > 0.1f;
            int ob = (b * KTOP + k) * 4;
            if (ob + 3 < out_size) {
                out[ob + 0] = valid ? ox1[bi] : 0.f;
                out[ob + 1] = valid ? oy1[bi] : 0.f;
                out[ob + 2] = valid ? ox2[bi] : 0.f;
                out[ob + 3] = valid ? oy2[bi] : 0.f;
            }
            int ol_idx = BK4 + b * KTOP + k;
            if (ol_idx < out_size) out[ol_idx] = valid ? (float)ol[bi] : 0.f;
            int oc_idx = BK4 + BK + b * KTOP + k;
            if (oc_idx < out_size) out[oc_idx] = valid ? oc[bi] : 0.f;
        }
    }
}

// ---------------- launch ---------------------------------------------------------
extern "C" void kernel_launch(void* const* d_in, const int* in_sizes, int n_in,
                              void* d_out, int out_size) {
    const float* x      = (const float*)d_in[0];
    const float* conv_w = (const float*)d_in[1];
    const float* conv_b = (const float*)d_in[2];
    const float* fc1_w  = (const float*)d_in[3];
    const float* fc1_b  = (const float*)d_in[4];
    const float* fc2_w  = (const float*)d_in[5];
    const float* fc2_b  = (const float*)d_in[6];
    float* out = (float*)d_out;

    float *A0, *part, *act1, *h1;
    cudaGetSymbolAddress((void**)&A0,   g_A0);
    cudaGetSymbolAddress((void**)&part, g_part);
    cudaGetSymbolAddress((void**)&act1, g_act1);
    cudaGetSymbolAddress((void**)&h1,   g_h1);

    cudaFuncSetAttribute(gemm_mma, cudaFuncAttributeMaxDynamicSharedMemorySize,
                         DSMEM_BYTES);

    // 1. gather subsampled input (smem transpose, coalesced writes)
    gather_kernel<<<dim3(20, 256), 256>>>(x);

    // 2. conv GEMM: (12544 x 1280) * (128 x 1280)^T, split-K=3 -> 294 CTAs
    gemm_mma<<<dim3(1, 98, 3), 256, DSMEM_BYTES>>>(A0, conv_w, part,
                                                   12544, 128, 1280, 432, 128);
    reduce_conv<<<(12544 * 128 + 255) / 256, 256>>>(part, conv_b);

    // 3. fc1 GEMM: (256 x 6272) * (4096 x 6272)^T, split-K=4 -> 256 CTAs
    gemm_mma<<<dim3(32, 2, 4), 256, DSMEM_BYTES>>>(act1, fc1_w, part,
                                                   256, 4096, 6272, 1568, 4096);
    reduce_fc1<<<(256 * 4096 + 255) / 256, 256>>>(part, fc1_b);

    // 4. fc2 GEMM: (256 x 4096) * (1470 x 4096)^T, split-K=12 -> 288 CTAs
    gemm_mma<<<dim3(12, 2, 12), 256, DSMEM_BYTES>>>(h1, fc2_w, part,
                                                    256, 1470, 4096, 352, 1536);
    reduce_fc2<<<(256 * 1470 + 255) / 256, 256>>>(part, fc2_b);

    // 5. decode + NMS
    decode_kernel<<<(BATCH * NBOX + 255) / 256, 256>>>();
    nms_kernel<<<BATCH, 128>>>(out, out_size);
}